// round 2
// baseline (speedup 1.0000x reference)
#include <cuda_runtime.h>
#include <cuda_bf16.h>

#define N_NODES 100000
#define N_EDGES 1600000
#define DFEAT   128
#define NSCAN_BLOCKS 98   // ceil(100000 / 1024)

// ---------------- scratch (static __device__, no allocs) ----------------
__device__ __align__(16) float g_h[N_NODES * DFEAT];     // post-GEMM features
__device__ __align__(16) float g_agg[N_NODES * DFEAT];   // post-aggregate (layer1 out)
__device__ float g_dinv[N_NODES];
__device__ int   g_cnt[N_NODES];
__device__ int   g_fill[N_NODES];
__device__ int   g_rowptr[N_NODES + 1];
__device__ int   g_blocksums[256];
__device__ int   g_col[N_EDGES];

typedef unsigned long long u64;

// ---------------- f32x2 helpers (Blackwell packed fp32) ----------------
__device__ __forceinline__ u64 pack2dup(float a) {
    u64 r;
    asm("mov.b64 %0, {%1, %1};" : "=l"(r) : "f"(a));
    return r;
}
__device__ __forceinline__ void fma2(u64 &c, u64 a, u64 b) {
    asm("fma.rn.f32x2 %0, %1, %2, %0;" : "+l"(c) : "l"(a), "l"(b));
}
__device__ __forceinline__ float2 unpack2(u64 v) {
    float2 f;
    asm("mov.b64 {%0, %1}, %2;" : "=f"(f.x), "=f"(f.y) : "l"(v));
    return f;
}

// ---------------- CSR build kernels ----------------
__global__ void k_zero() {
    int i = blockIdx.x * 256 + threadIdx.x;
    if (i < N_NODES) { g_cnt[i] = 0; g_fill[i] = 0; }
}

__global__ void k_hist(const int* __restrict__ dst) {
    int e = blockIdx.x * 256 + threadIdx.x;
    if (e < N_EDGES) atomicAdd(&g_cnt[dst[e]], 1);
}

__global__ void k_dinv() {
    int i = blockIdx.x * 256 + threadIdx.x;
    if (i < N_NODES) g_dinv[i] = rsqrtf((float)(g_cnt[i] + 1));  // +1 self loop
}

__global__ void k_scan1() {
    __shared__ int sd[256];
    int tid = threadIdx.x;
    int base = blockIdx.x * 1024 + tid * 4;
    int s = 0;
    #pragma unroll
    for (int c = 0; c < 4; ++c)
        if (base + c < N_NODES) s += g_cnt[base + c];
    sd[tid] = s;
    __syncthreads();
    #pragma unroll
    for (int off = 128; off > 0; off >>= 1) {
        if (tid < off) sd[tid] += sd[tid + off];
        __syncthreads();
    }
    if (tid == 0) g_blocksums[blockIdx.x] = sd[0];
}

__global__ void k_scan2() {
    __shared__ int sh[128];
    int tid = threadIdx.x;
    sh[tid] = (tid < NSCAN_BLOCKS) ? g_blocksums[tid] : 0;
    __syncthreads();
    #pragma unroll
    for (int off = 1; off < 128; off <<= 1) {
        int t = (tid >= off) ? sh[tid - off] : 0;
        __syncthreads();
        sh[tid] += t;
        __syncthreads();
    }
    int excl = (tid == 0) ? 0 : sh[tid - 1];
    if (tid < NSCAN_BLOCKS) g_blocksums[tid] = excl;
    if (tid == 0) g_rowptr[N_NODES] = N_EDGES;
}

__global__ void k_scan3() {
    __shared__ int sh[256];
    int tid = threadIdx.x;
    int base = blockIdx.x * 1024 + tid * 4;
    int c0 = 0, c1 = 0, c2 = 0, c3 = 0;
    if (base + 0 < N_NODES) c0 = g_cnt[base + 0];
    if (base + 1 < N_NODES) c1 = g_cnt[base + 1];
    if (base + 2 < N_NODES) c2 = g_cnt[base + 2];
    if (base + 3 < N_NODES) c3 = g_cnt[base + 3];
    sh[tid] = c0 + c1 + c2 + c3;
    __syncthreads();
    #pragma unroll
    for (int off = 1; off < 256; off <<= 1) {
        int t = (tid >= off) ? sh[tid - off] : 0;
        __syncthreads();
        sh[tid] += t;
        __syncthreads();
    }
    int excl = (tid == 0) ? 0 : sh[tid - 1];
    int e = g_blocksums[blockIdx.x] + excl;
    if (base + 0 < N_NODES) g_rowptr[base + 0] = e;
    if (base + 1 < N_NODES) g_rowptr[base + 1] = e + c0;
    if (base + 2 < N_NODES) g_rowptr[base + 2] = e + c0 + c1;
    if (base + 3 < N_NODES) g_rowptr[base + 3] = e + c0 + c1 + c2;
}

__global__ void k_fill(const int* __restrict__ src, const int* __restrict__ dst) {
    int e = blockIdx.x * 256 + threadIdx.x;
    if (e < N_EDGES) {
        int d = dst[e];
        int p = g_rowptr[d] + atomicAdd(&g_fill[d], 1);
        g_col[p] = src[e];
    }
}

// ---------------- GEMM: C[i][j] = sum_k A[i][k] * W[j][k]  (D=128) ----------------
// 128x128 block tile, BK=16, 256 threads, 8x8 per thread, packed f32x2 FMAs.
template <int PHASE>
__global__ __launch_bounds__(256, 2)
void k_gemm(const float* __restrict__ Aext, const float* __restrict__ W, int nrows) {
    const float* __restrict__ A = (PHASE == 0) ? Aext : g_agg;
    float* __restrict__ C = g_h;

    __shared__ __align__(16) float As[16][128];
    __shared__ __align__(16) float Bs[16][128];

    const int tid = threadIdx.x;
    const int tx = tid & 15;   // 16 col groups
    const int ty = tid >> 4;   // 16 row groups
    const int rowBase = blockIdx.x * 128;

    u64 c[8][4];
    #pragma unroll
    for (int i = 0; i < 8; ++i)
        #pragma unroll
        for (int j = 0; j < 4; ++j) c[i][j] = 0ull;

    for (int t = 0; t < 8; ++t) {
        const int kk = t * 16;
        __syncthreads();
        #pragma unroll
        for (int it = 0; it < 2; ++it) {
            int f = tid + it * 256;           // 0..511 float4 slots
            int r = f >> 2;
            int kc = (f & 3) * 4;
            int row = rowBase + r;
            float4 v = make_float4(0.f, 0.f, 0.f, 0.f);
            if (row < nrows)
                v = *reinterpret_cast<const float4*>(&A[row * 128 + kk + kc]);
            As[kc + 0][r] = v.x; As[kc + 1][r] = v.y;
            As[kc + 2][r] = v.z; As[kc + 3][r] = v.w;
            float4 w = *reinterpret_cast<const float4*>(&W[r * 128 + kk + kc]);
            Bs[kc + 0][r] = w.x; Bs[kc + 1][r] = w.y;
            Bs[kc + 2][r] = w.z; Bs[kc + 3][r] = w.w;
        }
        __syncthreads();

        #pragma unroll
        for (int k = 0; k < 16; ++k) {
            const float4 a0 = *reinterpret_cast<const float4*>(&As[k][ty * 8]);
            const float4 a1 = *reinterpret_cast<const float4*>(&As[k][ty * 8 + 4]);
            const u64* bp0 = reinterpret_cast<const u64*>(&Bs[k][tx * 4]);
            const u64* bp1 = reinterpret_cast<const u64*>(&Bs[k][64 + tx * 4]);
            u64 b0 = bp0[0], b1 = bp0[1], b2 = bp1[0], b3 = bp1[1];
            float av[8] = {a0.x, a0.y, a0.z, a0.w, a1.x, a1.y, a1.z, a1.w};
            #pragma unroll
            for (int i = 0; i < 8; ++i) {
                u64 aa = pack2dup(av[i]);
                fma2(c[i][0], aa, b0);
                fma2(c[i][1], aa, b1);
                fma2(c[i][2], aa, b2);
                fma2(c[i][3], aa, b3);
            }
        }
    }

    #pragma unroll
    for (int i = 0; i < 8; ++i) {
        int row = rowBase + ty * 8 + i;
        if (row < nrows) {
            float2 p0 = unpack2(c[i][0]), p1 = unpack2(c[i][1]);
            float4 o0 = make_float4(p0.x, p0.y, p1.x, p1.y);
            *reinterpret_cast<float4*>(&C[row * 128 + tx * 4]) = o0;
            float2 p2 = unpack2(c[i][2]), p3 = unpack2(c[i][3]);
            float4 o1 = make_float4(p2.x, p2.y, p3.x, p3.y);
            *reinterpret_cast<float4*>(&C[row * 128 + 64 + tx * 4]) = o1;
        }
    }
}

// ---------------- Aggregate: out[d] = dinv[d] * (sum_{s in N(d)} h[s]*dinv[s] + h[d]*dinv[d]) + b + perturb
// one warp per node, float4 per lane, CSR gather (no atomics)
template <int PHASE>
__global__ __launch_bounds__(256)
void k_agg(const float* __restrict__ bias, const float* __restrict__ perturb,
           float* __restrict__ outParam) {
    int gw = (blockIdx.x * 256 + threadIdx.x) >> 5;
    if (gw >= N_NODES) return;
    const int lane = threadIdx.x & 31;
    const float4* __restrict__ hv = reinterpret_cast<const float4*>(g_h);
    float* __restrict__ outp = (PHASE == 0) ? g_agg : outParam;

    const int d = gw;
    const float dd = g_dinv[d];
    float4 v = hv[d * 32 + lane];              // self loop (one dinv factor now)
    float ax = v.x * dd, ay = v.y * dd, az = v.z * dd, aw = v.w * dd;

    int j = g_rowptr[d];
    const int end = g_rowptr[d + 1];
    for (; j + 4 <= end; j += 4) {
        int s0 = g_col[j + 0], s1 = g_col[j + 1], s2 = g_col[j + 2], s3 = g_col[j + 3];
        float w0 = g_dinv[s0], w1 = g_dinv[s1], w2 = g_dinv[s2], w3 = g_dinv[s3];
        float4 v0 = hv[s0 * 32 + lane];
        float4 v1 = hv[s1 * 32 + lane];
        float4 v2 = hv[s2 * 32 + lane];
        float4 v3 = hv[s3 * 32 + lane];
        ax += v0.x * w0 + v1.x * w1 + v2.x * w2 + v3.x * w3;
        ay += v0.y * w0 + v1.y * w1 + v2.y * w2 + v3.y * w3;
        az += v0.z * w0 + v1.z * w1 + v2.z * w2 + v3.z * w3;
        aw += v0.w * w0 + v1.w * w1 + v2.w * w2 + v3.w * w3;
    }
    for (; j < end; ++j) {
        int s = g_col[j];
        float w = g_dinv[s];
        float4 vv = hv[s * 32 + lane];
        ax += vv.x * w; ay += vv.y * w; az += vv.z * w; aw += vv.w * w;
    }

    float4 b = reinterpret_cast<const float4*>(bias)[lane];
    float4 p = reinterpret_cast<const float4*>(perturb)[d * 32 + lane];
    float4 o;
    o.x = ax * dd + b.x + p.x;
    o.y = ay * dd + b.y + p.y;
    o.z = az * dd + b.z + p.z;
    o.w = aw * dd + b.w + p.w;
    reinterpret_cast<float4*>(outp)[d * 32 + lane] = o;
}

// ---------------- launch ----------------
extern "C" void kernel_launch(void* const* d_in, const int* in_sizes, int n_in,
                              void* d_out, int out_size) {
    const float* x  = (const float*)d_in[0];
    const int*   ei = (const int*)d_in[1];
    const float* pf = (const float*)d_in[2];
    const float* pl = (const float*)d_in[3];
    const float* W1 = (const float*)d_in[4];
    const float* b1 = (const float*)d_in[5];
    const float* W2 = (const float*)d_in[6];
    const float* b2 = (const float*)d_in[7];
    float* out = (float*)d_out;
    const int* src = ei;
    const int* dst = ei + N_EDGES;

    const int nb_nodes = (N_NODES + 255) / 256;       // 391
    const int nb_edges = (N_EDGES + 255) / 256;       // 6250
    const int nb_gemm  = (N_NODES + 127) / 128;       // 782
    const int nb_agg   = (N_NODES + 7) / 8;           // 12500

    // CSR + norm build (per call; depends only on edge_index -> deterministic work)
    k_zero<<<nb_nodes, 256>>>();
    k_hist<<<nb_edges, 256>>>(dst);
    k_dinv<<<nb_nodes, 256>>>();
    k_scan1<<<NSCAN_BLOCKS, 256>>>();
    k_scan2<<<1, 128>>>();
    k_scan3<<<NSCAN_BLOCKS, 256>>>();
    k_fill<<<nb_edges, 256>>>(src, dst);

    // layer 1
    k_gemm<0><<<nb_gemm, 256>>>(x, W1, N_NODES);
    k_agg<0><<<nb_agg, 256>>>(b1, pf, nullptr);
    // layer 2
    k_gemm<1><<<nb_gemm, 256>>>(nullptr, W2, N_NODES);
    k_agg<1><<<nb_agg, 256>>>(b2, pl, out);
}